// round 1
// baseline (speedup 1.0000x reference)
#include <cuda_runtime.h>
#include <cuda_bf16.h>

// Mat2Twist: rotation matrix (3x3) -> axis-angle vector (3).
// B = in_sizes[0]/9 matrices. Memory-bound elementwise map.
//
// Strategy: smem staging for perfectly coalesced float4 global loads/stores.
// Each block of 256 threads handles 256 matrices:
//   - 2304 input floats = 576 float4, loaded coalesced into smem
//   - per-thread compute from smem (stride-9 word reads: conflict-free)
//   - 768 output floats staged in smem (stride-3 writes: conflict-free),
//     then written as 192 coalesced float4.

#define TPB 256

__global__ __launch_bounds__(TPB) void mat2twist_kernel(
    const float* __restrict__ in, float* __restrict__ out, int n)
{
    __shared__ float s_in[TPB * 9];    // 9216 B
    __shared__ float s_out[TPB * 3];   // 3072 B

    const int tid = threadIdx.x;
    const int blockMat = blockIdx.x * TPB;

    if (blockMat + TPB <= n) {
        // ---- fast path: full block, vectorized staging ----
        const float4* __restrict__ gin =
            reinterpret_cast<const float4*>(in + (size_t)blockMat * 9);
        float4* s_in4 = reinterpret_cast<float4*>(s_in);
        // 576 float4 per block
        #pragma unroll
        for (int i = tid; i < (TPB * 9) / 4; i += TPB)
            s_in4[i] = gin[i];
        __syncthreads();

        const float* m = &s_in[tid * 9];
        float m00 = m[0], m01 = m[1], m02 = m[2];
        float m10 = m[3], m11 = m[4], m12 = m[5];
        float m20 = m[6], m21 = m[7], m22 = m[8];

        float c = 0.5f * (m00 + m11 + m22 - 1.0f);
        c = fminf(1.0f, fmaxf(-1.0f, c));
        float angle = acosf(c);
        float scale = angle / (2.0f * sinf(angle));

        s_out[tid * 3 + 0] = scale * (m21 - m12);
        s_out[tid * 3 + 1] = scale * (m02 - m20);
        s_out[tid * 3 + 2] = scale * (m10 - m01);
        __syncthreads();

        float4* __restrict__ gout =
            reinterpret_cast<float4*>(out + (size_t)blockMat * 3);
        const float4* s_out4 = reinterpret_cast<const float4*>(s_out);
        // 192 float4 per block
        if (tid < (TPB * 3) / 4)
            gout[tid] = s_out4[tid];
    } else {
        // ---- tail path: scalar, bounds-checked ----
        int i = blockMat + tid;
        if (i < n) {
            const float* m = in + (size_t)i * 9;
            float m00 = m[0], m01 = m[1], m02 = m[2];
            float m10 = m[3], m11 = m[4], m12 = m[5];
            float m20 = m[6], m21 = m[7], m22 = m[8];

            float c = 0.5f * (m00 + m11 + m22 - 1.0f);
            c = fminf(1.0f, fmaxf(-1.0f, c));
            float angle = acosf(c);
            float scale = angle / (2.0f * sinf(angle));

            out[(size_t)i * 3 + 0] = scale * (m21 - m12);
            out[(size_t)i * 3 + 1] = scale * (m02 - m20);
            out[(size_t)i * 3 + 2] = scale * (m10 - m01);
        }
    }
}

extern "C" void kernel_launch(void* const* d_in, const int* in_sizes, int n_in,
                              void* d_out, int out_size)
{
    const float* in = (const float*)d_in[0];
    float* out = (float*)d_out;
    int n = in_sizes[0] / 9;           // number of matrices
    int grid = (n + TPB - 1) / TPB;
    mat2twist_kernel<<<grid, TPB>>>(in, out, n);
}